// round 14
// baseline (speedup 1.0000x reference)
#include <cuda_runtime.h>
#include <cstdint>

#define W 131072
#define J 21
#define NB 20
#define BLOCK 256
#define GRID 2048
#define WPB (BLOCK / 32)
#define NWARP (GRID * WPB)                 // 16384 warps
#define CHUNK (W / NWARP)                  // 8 frames per warp (exact)
#define NSTEP (CHUNK / 2)                  // 4 steps of 2 frames

// weights folded with denominators
#define C_PROJ   (1.0f / 42.0f)
#define C_BONE   (1.0f / 20.0f)
#define C_SMOOTH (0.5f / 63.0f)
#define C_LIFT   (0.1f / 63.0f)

#define FULL 0xFFFFFFFFu

__device__ double g_acc;           // zero at load; last block resets each call
__device__ unsigned int g_count;   // wraps to 0 via atomicInc

__global__ __launch_bounds__(BLOCK, 5)
void loss_kernel(const float* __restrict__ pose,   // [(W+1),3,J]
                 const float* __restrict__ cam,    // [W,2,3]
                 const float* __restrict__ p2d,    // [W,2,J]
                 const float* __restrict__ blen,   // [NB]
                 const float* __restrict__ lift,   // [W,3,NB]
                 const int*   __restrict__ bc,     // [NB,2]
                 const int*   __restrict__ lbc,    // [NB,2]
                 float* __restrict__ out)
{
    const int tid  = threadIdx.x;
    const int lane = tid & 31;
    const int wid  = tid >> 5;
    const int gw   = blockIdx.x * WPB + wid;
    const int f0   = gw * CHUNK;

    const bool jok = lane < J;
    const bool bok = lane < NB;

    int ch = 0, pa = 0, lch = 0, lpa = 0;
    float bl = 0.0f;
    if (bok) {
        ch  = bc[2 * lane];
        pa  = bc[2 * lane + 1];
        lch = lbc[2 * lane];
        lpa = lbc[2 * lane + 1];
        bl  = blen[lane];
    }
    // warp-uniform structure checks (generic fallbacks preserved)
    const bool same_conn = __all_sync(FULL, !bok || (lch == ch && lpa == pa));
    const bool chain     = __all_sync(FULL, !bok || (ch == lane + 1 && pa == lane));

    float acc = 0.0f;

    // double-buffered per-step register sets (fully unrolled -> registers)
    float X1[2], Y1[2], Z1[2], X2[2], Y2[2], Z2[2];
    float QX1[2], QY1[2], QX2[2], QY2[2];
    float LX1[2], LY1[2], LZ1[2], LX2[2], LY2[2], LZ2[2];

    // ---- lead-in history: x0 = frame f0, xm = frame max(f0-1,0) ----
    const float* pA = pose + (size_t)f0 * 63;
    float x0 = jok ? pA[lane]          : 0.0f;
    float y0 = jok ? pA[J + lane]      : 0.0f;
    float z0 = jok ? pA[2 * J + lane]  : 0.0f;
    const float* pB = pose + (size_t)(f0 > 0 ? f0 - 1 : 0) * 63;
    float xm = jok ? pB[lane]          : 0.0f;
    float ym = jok ? pB[J + lane]      : 0.0f;
    float zm = jok ? pB[2 * J + lane]  : 0.0f;

    // ---- prologue: load step 0 into buffer 0 ----
    {
        const int w = f0;
        const float* pf1 = pose + (size_t)(w + 1) * 63;
        X1[0] = jok ? pf1[lane]         : 0.0f;
        Y1[0] = jok ? pf1[J + lane]     : 0.0f;
        Z1[0] = jok ? pf1[2 * J + lane] : 0.0f;
        const float* pf2 = pf1 + 63;
        X2[0] = jok ? pf2[lane]         : 0.0f;
        Y2[0] = jok ? pf2[J + lane]     : 0.0f;
        Z2[0] = jok ? pf2[2 * J + lane] : 0.0f;
        const float* qa = p2d + (size_t)w * 42;
        QX1[0] = jok ? qa[lane]     : 0.0f;
        QY1[0] = jok ? qa[J + lane] : 0.0f;
        QX2[0] = jok ? qa[42 + lane]     : 0.0f;
        QY2[0] = jok ? qa[42 + J + lane] : 0.0f;
        const float* la = lift + (size_t)w * 60;
        LX1[0] = bok ? la[lane]          : 0.0f;
        LY1[0] = bok ? la[NB + lane]     : 0.0f;
        LZ1[0] = bok ? la[2 * NB + lane] : 0.0f;
        LX2[0] = bok ? la[60 + lane]          : 0.0f;
        LY2[0] = bok ? la[60 + NB + lane]     : 0.0f;
        LZ2[0] = bok ? la[60 + 2 * NB + lane] : 0.0f;
    }

    // frame-0 bone term (done once, by the warp owning frame 0)
    if (f0 == 0) {
        float dx = __shfl_sync(FULL, x0, ch) - __shfl_sync(FULL, x0, pa);
        float dy = __shfl_sync(FULL, y0, ch) - __shfl_sync(FULL, y0, pa);
        float dz = __shfl_sync(FULL, z0, ch) - __shfl_sync(FULL, z0, pa);
        float len = dx * dx + dy * dy + dz * dz;
        float e = len - bl;
        if (bok) acc += C_BONE * e * e;
    }

    #pragma unroll
    for (int s = 0; s < NSTEP; s++) {
        const int cur = s & 1;
        const int nxt = cur ^ 1;
        const int w   = f0 + 2 * s;

        // ===== prefetch step s+1 (hidden behind this step's compute) =====
        if (s + 1 < NSTEP) {
            const int wn = w + 2;
            const float* pf1 = pose + (size_t)(wn + 1) * 63;
            X1[nxt] = jok ? pf1[lane]         : 0.0f;
            Y1[nxt] = jok ? pf1[J + lane]     : 0.0f;
            Z1[nxt] = jok ? pf1[2 * J + lane] : 0.0f;
            const float* pf2 = pf1 + 63;
            X2[nxt] = jok ? pf2[lane]         : 0.0f;
            Y2[nxt] = jok ? pf2[J + lane]     : 0.0f;
            Z2[nxt] = jok ? pf2[2 * J + lane] : 0.0f;
            const float* qa = p2d + (size_t)wn * 42;
            QX1[nxt] = jok ? qa[lane]     : 0.0f;
            QY1[nxt] = jok ? qa[J + lane] : 0.0f;
            QX2[nxt] = jok ? qa[42 + lane]     : 0.0f;
            QY2[nxt] = jok ? qa[42 + J + lane] : 0.0f;
            const float* la = lift + (size_t)wn * 60;
            LX1[nxt] = bok ? la[lane]          : 0.0f;
            LY1[nxt] = bok ? la[NB + lane]     : 0.0f;
            LZ1[nxt] = bok ? la[2 * NB + lane] : 0.0f;
            LX2[nxt] = bok ? la[60 + lane]          : 0.0f;
            LY2[nxt] = bok ? la[60 + NB + lane]     : 0.0f;
            LZ2[nxt] = bok ? la[60 + 2 * NB + lane] : 0.0f;
        }

        const float x1 = X1[cur], y1 = Y1[cur], z1 = Z1[cur];
        const float x2 = X2[cur], y2 = Y2[cur], z2 = Z2[cur];

        // ======== frame w ========
        {
            const float2* c = (const float2*)(cam + (size_t)w * 6);
            float2 c0 = c[0], c1 = c[1], c2 = c[2];
            float px = c0.x * x1 + c0.y * y1 + c1.x * z1 - QX1[cur];
            float py = c1.y * x1 + c2.x * y1 + c2.y * z1 - QY1[cur];
            if (jok) acc += C_PROJ * (px * px + py * py);

            if (w >= 1 || s > 0) {
                float a0 = x1 - 2.0f * x0 + xm;
                float a1 = y1 - 2.0f * y0 + ym;
                float a2 = z1 - 2.0f * z0 + zm;
                if (jok) acc += C_SMOOTH * (a0 * a0 + a1 * a1 + a2 * a2);
            }

            float bx, by, bz;
            if (chain) {
                bx = __shfl_down_sync(FULL, x1, 1) - x1;
                by = __shfl_down_sync(FULL, y1, 1) - y1;
                bz = __shfl_down_sync(FULL, z1, 1) - z1;
            } else {
                bx = __shfl_sync(FULL, x1, ch) - __shfl_sync(FULL, x1, pa);
                by = __shfl_sync(FULL, y1, ch) - __shfl_sync(FULL, y1, pa);
                bz = __shfl_sync(FULL, z1, ch) - __shfl_sync(FULL, z1, pa);
            }
            float len = bx * bx + by * by + bz * bz;
            float e = len - bl;
            if (bok) acc += C_BONE * e * e;

            float ux, uy, uz;
            if (same_conn) { ux = bx; uy = by; uz = bz; }
            else {
                ux = __shfl_sync(FULL, x1, lch) - __shfl_sync(FULL, x1, lpa);
                uy = __shfl_sync(FULL, y1, lch) - __shfl_sync(FULL, y1, lpa);
                uz = __shfl_sync(FULL, z1, lch) - __shfl_sync(FULL, z1, lpa);
            }
            float inv = bok ? (1.0f / sqrtf(ux * ux + uy * uy + uz * uz)) : 0.0f;
            float ex = LX1[cur] - ux * inv;
            float ey = LY1[cur] - uy * inv;
            float ez = LZ1[cur] - uz * inv;
            if (bok) acc += C_LIFT * (ex * ex + ey * ey + ez * ez);
        }

        // ======== frame w+1 ========
        {
            const float2* c = (const float2*)(cam + (size_t)(w + 1) * 6);
            float2 c0 = c[0], c1 = c[1], c2 = c[2];
            float px = c0.x * x2 + c0.y * y2 + c1.x * z2 - QX2[cur];
            float py = c1.y * x2 + c2.x * y2 + c2.y * z2 - QY2[cur];
            if (jok) acc += C_PROJ * (px * px + py * py);

            float a0 = x2 - 2.0f * x1 + x0;
            float a1 = y2 - 2.0f * y1 + y0;
            float a2 = z2 - 2.0f * z1 + z0;
            if (jok) acc += C_SMOOTH * (a0 * a0 + a1 * a1 + a2 * a2);

            float bx, by, bz;
            if (chain) {
                bx = __shfl_down_sync(FULL, x2, 1) - x2;
                by = __shfl_down_sync(FULL, y2, 1) - y2;
                bz = __shfl_down_sync(FULL, z2, 1) - z2;
            } else {
                bx = __shfl_sync(FULL, x2, ch) - __shfl_sync(FULL, x2, pa);
                by = __shfl_sync(FULL, y2, ch) - __shfl_sync(FULL, y2, pa);
                bz = __shfl_sync(FULL, z2, ch) - __shfl_sync(FULL, z2, pa);
            }
            float len = bx * bx + by * by + bz * bz;
            float e = len - bl;
            if (bok) acc += C_BONE * e * e;

            float ux, uy, uz;
            if (same_conn) { ux = bx; uy = by; uz = bz; }
            else {
                ux = __shfl_sync(FULL, x2, lch) - __shfl_sync(FULL, x2, lpa);
                uy = __shfl_sync(FULL, y2, lch) - __shfl_sync(FULL, y2, lpa);
                uz = __shfl_sync(FULL, z2, lch) - __shfl_sync(FULL, z2, lpa);
            }
            float inv = bok ? (1.0f / sqrtf(ux * ux + uy * uy + uz * uz)) : 0.0f;
            float ex = LX2[cur] - ux * inv;
            float ey = LY2[cur] - uy * inv;
            float ez = LZ2[cur] - uz * inv;
            if (bok) acc += C_LIFT * (ex * ex + ey * ey + ez * ez);
        }

        // rotate history: prev = pose[w+1], cur = pose[w+2]
        xm = x1; ym = y1; zm = z1;
        x0 = x2; y0 = y2; z0 = z2;
    }

    // ---- warp reduction ----
    #pragma unroll
    for (int off = 16; off > 0; off >>= 1)
        acc += __shfl_down_sync(FULL, acc, off);

    __shared__ float warp_sums[WPB];
    __shared__ bool  is_last;
    if (lane == 0) warp_sums[wid] = acc;
    __syncthreads();

    if (wid == 0) {
        float v = (lane < WPB) ? warp_sums[lane] : 0.0f;
        #pragma unroll
        for (int off = 4; off > 0; off >>= 1)
            v += __shfl_down_sync(FULL, v, off);
        if (lane == 0) {
            atomicAdd(&g_acc, (double)v);
            __threadfence();
            unsigned int ticket = atomicInc(&g_count, GRID - 1);
            is_last = (ticket == GRID - 1);
        }
    }
    __syncthreads();

    if (is_last && tid == 0) {
        __threadfence();
        out[0] = (float)g_acc;
        g_acc = 0.0;   // reset for next graph replay (g_count already wrapped)
        __threadfence();
    }
}

extern "C" void kernel_launch(void* const* d_in, const int* in_sizes, int n_in,
                              void* d_out, int out_size)
{
    const float* pose = (const float*)d_in[0];
    const float* cam  = (const float*)d_in[1];
    const float* p2d  = (const float*)d_in[2];
    const float* blen = (const float*)d_in[3];
    const float* lift = (const float*)d_in[4];
    const int*   bc   = (const int*)d_in[5];
    const int*   lbc  = (const int*)d_in[6];
    float* out = (float*)d_out;

    loss_kernel<<<GRID, BLOCK>>>(pose, cam, p2d, blen, lift, bc, lbc, out);
}

// round 15
// speedup vs baseline: 1.4947x; 1.4947x over previous
#include <cuda_runtime.h>
#include <cstdint>

#define W 131072
#define J 21
#define NB 20
#define BLOCK 256
#define GRID 2048
#define WPB (BLOCK / 32)
#define NWARP (GRID * WPB)                 // 16384 warps
#define CHUNK (W / NWARP)                  // 8 frames per warp (exact)
#define NSTEP (CHUNK / 2)                  // 4 steps of 2 frames

#define WBUF 344                            // floats per warp buffer (342 + pad)
// buffer layout (per 2-frame step at base frame w):
//   [0..62]    pose frame w+1
//   [63..125]  pose frame w+2
//   [126..167] p2d  frame w
//   [168..209] p2d  frame w+1
//   [210..269] lift frame w
//   [270..329] lift frame w+1
//   [330..335] cam  frame w
//   [336..341] cam  frame w+1

// weights folded with denominators
#define C_PROJ   (1.0f / 42.0f)
#define C_BONE   (1.0f / 20.0f)
#define C_SMOOTH (0.5f / 63.0f)
#define C_LIFT   (0.1f / 63.0f)

#define FULL 0xFFFFFFFFu

__device__ double g_acc;           // zero at load; last block resets each call
__device__ unsigned int g_count;   // wraps to 0 via atomicInc

__global__ __launch_bounds__(BLOCK)
void loss_kernel(const float* __restrict__ pose,   // [(W+1),3,J]
                 const float* __restrict__ cam,    // [W,2,3]
                 const float* __restrict__ p2d,    // [W,2,J]
                 const float* __restrict__ blen,   // [NB]
                 const float* __restrict__ lift,   // [W,3,NB]
                 const int*   __restrict__ bc,     // [NB,2]
                 const int*   __restrict__ lbc,    // [NB,2]
                 float* __restrict__ out)
{
    __shared__ float s_buf[2][WPB][WBUF];

    const int tid  = threadIdx.x;
    const int lane = tid & 31;
    const int wid  = tid >> 5;
    const int gw   = blockIdx.x * WPB + wid;
    const int f0   = gw * CHUNK;

    const bool jok = lane < J;
    const bool bok = lane < NB;

    int ch = 0, pa = 0, lch = 0, lpa = 0;
    float bl = 0.0f;
    if (bok) {
        ch  = bc[2 * lane];
        pa  = bc[2 * lane + 1];
        lch = lbc[2 * lane];
        lpa = lbc[2 * lane + 1];
        bl  = blen[lane];
    }
    const bool same_conn = __all_sync(FULL, !bok || (lch == ch && lpa == pa));

    float acc = 0.0f;

    float* bufA = s_buf[0][wid];
    float* bufB = s_buf[1][wid];

    // ---- lead-in history: x0 = frame f0, xm = frame max(f0-1,0) ----
    const float* pA = pose + (size_t)f0 * 63;
    float x0 = jok ? pA[lane]          : 0.0f;
    float y0 = jok ? pA[J + lane]      : 0.0f;
    float z0 = jok ? pA[2 * J + lane]  : 0.0f;
    const float* pB = pose + (size_t)(f0 > 0 ? f0 - 1 : 0) * 63;
    float xm = jok ? pB[lane]          : 0.0f;
    float ym = jok ? pB[J + lane]      : 0.0f;
    float zm = jok ? pB[2 * J + lane]  : 0.0f;

    // frame-0 bone term (done once, by the warp owning frame 0)
    if (f0 == 0) {
        float dx = __shfl_sync(FULL, x0, ch) - __shfl_sync(FULL, x0, pa);
        float dy = __shfl_sync(FULL, y0, ch) - __shfl_sync(FULL, y0, pa);
        float dz = __shfl_sync(FULL, z0, ch) - __shfl_sync(FULL, z0, pa);
        float len = dx * dx + dy * dy + dz * dz;
        float e = len - bl;
        if (bok) acc += C_BONE * e * e;
    }

    // ---- prologue: fetch + store step 0 into bufA ----
    {
        const int w = f0;
        const float* ps = pose + (size_t)(w + 1) * 63;   // 126 floats
        const float* qs = p2d  + (size_t)w * 42;          // 84 floats
        const float* ls = lift + (size_t)w * 60;          // 120 floats
        const float* cs = cam  + (size_t)w * 6;           // 12 floats

        float r0 = ps[lane];
        float r1 = ps[32 + lane];
        float r2 = ps[64 + lane];
        float r3 = (lane < 30) ? ps[96 + lane] : 0.0f;
        float r4 = qs[lane];
        float r5 = qs[32 + lane];
        float r6 = (lane < 20) ? qs[64 + lane] : 0.0f;
        float r7 = ls[lane];
        float r8 = ls[32 + lane];
        float r9 = ls[64 + lane];
        float r10 = (lane < 24) ? ls[96 + lane] : 0.0f;
        float r11 = (lane < 12) ? cs[lane] : 0.0f;

        bufA[lane]       = r0;
        bufA[32 + lane]  = r1;
        bufA[64 + lane]  = r2;
        if (lane < 30) bufA[96 + lane] = r3;
        bufA[126 + lane]      = r4;
        bufA[126 + 32 + lane] = r5;
        if (lane < 20) bufA[126 + 64 + lane] = r6;
        bufA[210 + lane]      = r7;
        bufA[210 + 32 + lane] = r8;
        bufA[210 + 64 + lane] = r9;
        if (lane < 24) bufA[210 + 96 + lane] = r10;
        if (lane < 12) bufA[330 + lane] = r11;
        __syncwarp();
    }

    #pragma unroll
    for (int s = 0; s < NSTEP; s++) {
        const int w = f0 + 2 * s;
        float* cur = bufA;
        float* nxt = bufB;

        // ===== issue prefetch LDGs for step s+1 (dense 32-lane loads) =====
        float r0, r1, r2, r3, r4, r5, r6, r7, r8, r9, r10, r11;
        if (s + 1 < NSTEP) {
            const int wn = w + 2;
            const float* ps = pose + (size_t)(wn + 1) * 63;
            const float* qs = p2d  + (size_t)wn * 42;
            const float* ls = lift + (size_t)wn * 60;
            const float* cs = cam  + (size_t)wn * 6;
            r0 = ps[lane];
            r1 = ps[32 + lane];
            r2 = ps[64 + lane];
            r3 = (lane < 30) ? ps[96 + lane] : 0.0f;
            r4 = qs[lane];
            r5 = qs[32 + lane];
            r6 = (lane < 20) ? qs[64 + lane] : 0.0f;
            r7 = ls[lane];
            r8 = ls[32 + lane];
            r9 = ls[64 + lane];
            r10 = (lane < 24) ? ls[96 + lane] : 0.0f;
            r11 = (lane < 12) ? cs[lane] : 0.0f;
        }

        // ===== compute step s from cur (LDS hits, hides prefetch latency) =====
        const float x1 = cur[lane];
        const float y1 = cur[21 + lane];
        const float z1 = cur[42 + lane];
        const float x2 = cur[63 + lane];
        const float y2 = cur[63 + 21 + lane];
        const float z2 = cur[63 + 42 + lane];

        // ---- frame w ----
        {
            float c0 = cur[330], c1 = cur[331], c2 = cur[332];
            float c3 = cur[333], c4 = cur[334], c5 = cur[335];
            float px = c0 * x1 + c1 * y1 + c2 * z1 - cur[126 + lane];
            float py = c3 * x1 + c4 * y1 + c5 * z1 - cur[126 + 21 + lane];
            if (jok) acc += C_PROJ * (px * px + py * py);

            if (w >= 1 || s > 0) {
                float a0 = x1 - 2.0f * x0 + xm;
                float a1 = y1 - 2.0f * y0 + ym;
                float a2 = z1 - 2.0f * z0 + zm;
                if (jok) acc += C_SMOOTH * (a0 * a0 + a1 * a1 + a2 * a2);
            }

            float bx = __shfl_sync(FULL, x1, ch) - __shfl_sync(FULL, x1, pa);
            float by = __shfl_sync(FULL, y1, ch) - __shfl_sync(FULL, y1, pa);
            float bz = __shfl_sync(FULL, z1, ch) - __shfl_sync(FULL, z1, pa);
            float len = bx * bx + by * by + bz * bz;
            float e = len - bl;
            if (bok) acc += C_BONE * e * e;

            float ux, uy, uz;
            if (same_conn) { ux = bx; uy = by; uz = bz; }
            else {
                ux = __shfl_sync(FULL, x1, lch) - __shfl_sync(FULL, x1, lpa);
                uy = __shfl_sync(FULL, y1, lch) - __shfl_sync(FULL, y1, lpa);
                uz = __shfl_sync(FULL, z1, lch) - __shfl_sync(FULL, z1, lpa);
            }
            float inv = bok ? (1.0f / sqrtf(ux * ux + uy * uy + uz * uz)) : 0.0f;
            float ex = cur[210 + lane]      - ux * inv;
            float ey = cur[210 + 20 + lane] - uy * inv;
            float ez = cur[210 + 40 + lane] - uz * inv;
            if (bok) acc += C_LIFT * (ex * ex + ey * ey + ez * ez);
        }

        // ---- frame w+1 ----
        {
            float c0 = cur[336], c1 = cur[337], c2 = cur[338];
            float c3 = cur[339], c4 = cur[340], c5 = cur[341];
            float px = c0 * x2 + c1 * y2 + c2 * z2 - cur[168 + lane];
            float py = c3 * x2 + c4 * y2 + c5 * z2 - cur[168 + 21 + lane];
            if (jok) acc += C_PROJ * (px * px + py * py);

            float a0 = x2 - 2.0f * x1 + x0;
            float a1 = y2 - 2.0f * y1 + y0;
            float a2 = z2 - 2.0f * z1 + z0;
            if (jok) acc += C_SMOOTH * (a0 * a0 + a1 * a1 + a2 * a2);

            float bx = __shfl_sync(FULL, x2, ch) - __shfl_sync(FULL, x2, pa);
            float by = __shfl_sync(FULL, y2, ch) - __shfl_sync(FULL, y2, pa);
            float bz = __shfl_sync(FULL, z2, ch) - __shfl_sync(FULL, z2, pa);
            float len = bx * bx + by * by + bz * bz;
            float e = len - bl;
            if (bok) acc += C_BONE * e * e;

            float ux, uy, uz;
            if (same_conn) { ux = bx; uy = by; uz = bz; }
            else {
                ux = __shfl_sync(FULL, x2, lch) - __shfl_sync(FULL, x2, lpa);
                uy = __shfl_sync(FULL, y2, lch) - __shfl_sync(FULL, y2, lpa);
                uz = __shfl_sync(FULL, z2, lch) - __shfl_sync(FULL, z2, lpa);
            }
            float inv = bok ? (1.0f / sqrtf(ux * ux + uy * uy + uz * uz)) : 0.0f;
            float ex = cur[270 + lane]      - ux * inv;
            float ey = cur[270 + 20 + lane] - uy * inv;
            float ez = cur[270 + 40 + lane] - uz * inv;
            if (bok) acc += C_LIFT * (ex * ex + ey * ey + ez * ez);
        }

        // ===== store prefetched data to nxt, then swap =====
        if (s + 1 < NSTEP) {
            nxt[lane]       = r0;
            nxt[32 + lane]  = r1;
            nxt[64 + lane]  = r2;
            if (lane < 30) nxt[96 + lane] = r3;
            nxt[126 + lane]      = r4;
            nxt[126 + 32 + lane] = r5;
            if (lane < 20) nxt[126 + 64 + lane] = r6;
            nxt[210 + lane]      = r7;
            nxt[210 + 32 + lane] = r8;
            nxt[210 + 64 + lane] = r9;
            if (lane < 24) nxt[210 + 96 + lane] = r10;
            if (lane < 12) nxt[330 + lane] = r11;
            __syncwarp();
        }

        // rotate history: prev = pose[w+1], cur = pose[w+2]
        xm = x1; ym = y1; zm = z1;
        x0 = x2; y0 = y2; z0 = z2;

        // swap buffers (register pointers, compile-time after unroll)
        float* t = bufA; bufA = bufB; bufB = t;
    }

    // ---- warp reduction ----
    #pragma unroll
    for (int off = 16; off > 0; off >>= 1)
        acc += __shfl_down_sync(FULL, acc, off);

    __shared__ float warp_sums[WPB];
    __shared__ bool  is_last;
    if (lane == 0) warp_sums[wid] = acc;
    __syncthreads();

    if (wid == 0) {
        float v = (lane < WPB) ? warp_sums[lane] : 0.0f;
        #pragma unroll
        for (int off = 4; off > 0; off >>= 1)
            v += __shfl_down_sync(FULL, v, off);
        if (lane == 0) {
            atomicAdd(&g_acc, (double)v);
            __threadfence();
            unsigned int ticket = atomicInc(&g_count, GRID - 1);
            is_last = (ticket == GRID - 1);
        }
    }
    __syncthreads();

    if (is_last && tid == 0) {
        __threadfence();
        out[0] = (float)g_acc;
        g_acc = 0.0;   // reset for next graph replay (g_count already wrapped)
        __threadfence();
    }
}

extern "C" void kernel_launch(void* const* d_in, const int* in_sizes, int n_in,
                              void* d_out, int out_size)
{
    const float* pose = (const float*)d_in[0];
    const float* cam  = (const float*)d_in[1];
    const float* p2d  = (const float*)d_in[2];
    const float* blen = (const float*)d_in[3];
    const float* lift = (const float*)d_in[4];
    const int*   bc   = (const int*)d_in[5];
    const int*   lbc  = (const int*)d_in[6];
    float* out = (float*)d_out;

    loss_kernel<<<GRID, BLOCK>>>(pose, cam, p2d, blen, lift, bc, lbc, out);
}